// round 3
// baseline (speedup 1.0000x reference)
#include <cuda_runtime.h>
#include <math.h>

// ChamferLoss: B=4, N=8192, K=8 nearest neighbors, L2 norm.
// loss = sum over all (query, knn) exact distances / (B*N*K), both directions.

namespace {
constexpr int B_      = 4;
constexpr int N_      = 8192;
constexpr int KNN     = 8;
constexpr int THREADS = 128;
constexpr int QPT     = 2;                    // queries per thread
constexpr int QPB     = THREADS * QPT;        // 256 queries per block
constexpr int CHUNK   = 2048;                 // candidate tile (32 KB smem)
constexpr int NCHUNK  = N_ / CHUNK;           // 4
constexpr int QCHUNKS = N_ / QPB;             // 32
constexpr int BLOCKS  = B_ * 2 * QCHUNKS;     // 256 (dir x batch x query-chunk)
}

// Deterministic reduction scratch (no atomics, no allocation).
__device__ float g_partials[BLOCKS];

__global__ __launch_bounds__(THREADS)
void chamfer_knn_kernel(const float* __restrict__ src,
                        const float* __restrict__ tgt,
                        const float* __restrict__ flow)
{
    __shared__ __align__(16) float4 sC[CHUNK];   // candidate tile, w unused
    float* sCf = reinterpret_cast<float*>(sC);

    const int tid    = threadIdx.x;
    const int bi     = blockIdx.x;
    const int chunkq = bi % QCHUNKS;       // which 256-query slice
    const int bd     = bi / QCHUNKS;
    const int dir    = bd & 1;             // 0: pred->tgt, 1: tgt->pred
    const int b      = bd >> 1;

    const float* __restrict__ sbase = src  + (size_t)b * N_ * 3;
    const float* __restrict__ tbase = tgt  + (size_t)b * N_ * 3;
    const float* __restrict__ fbase = flow + (size_t)b * N_ * 3;

    // ---- load this thread's queries ----
    float qx[QPT], qy[QPT], qz[QPT];
#pragma unroll
    for (int u = 0; u < QPT; ++u) {
        const int qi = chunkq * QPB + u * THREADS + tid;
        if (dir == 0) {
            // query = pc_pred = src + flow; candidates = tgt
            qx[u] = sbase[3 * qi + 0] + fbase[3 * qi + 0];
            qy[u] = sbase[3 * qi + 1] + fbase[3 * qi + 1];
            qz[u] = sbase[3 * qi + 2] + fbase[3 * qi + 2];
        } else {
            // query = tgt; candidates = pc_pred
            qx[u] = tbase[3 * qi + 0];
            qy[u] = tbase[3 * qi + 1];
            qz[u] = tbase[3 * qi + 2];
        }
    }

    // ---- per-query sorted min-8 of squared distances (ascending, h[7]=max) ----
    float h[QPT][KNN];
#pragma unroll
    for (int u = 0; u < QPT; ++u)
#pragma unroll
        for (int i = 0; i < KNN; ++i) h[u][i] = 3.0e38f;

    for (int ch = 0; ch < NCHUNK; ++ch) {
        __syncthreads();   // previous tile fully consumed
        // cooperative, coalesced tile load (float-linear), AoS float4 in smem
        const int gbase = ch * CHUNK * 3;
        for (int t = tid; t < CHUNK * 3; t += THREADS) {
            float v;
            if (dir == 0) v = tbase[gbase + t];
            else          v = sbase[gbase + t] + fbase[gbase + t];
            const int p = t / 3;
            sCf[p * 4 + (t - 3 * p)] = v;
        }
        __syncthreads();

#pragma unroll 4
        for (int j = 0; j < CHUNK; ++j) {
            const float4 c4 = sC[j];     // broadcast LDS.128
#pragma unroll
            for (int u = 0; u < QPT; ++u) {
                const float dx = qx[u] - c4.x;
                const float dy = qy[u] - c4.y;
                const float dz = qz[u] - c4.z;
                const float d2 = fmaf(dx, dx, fmaf(dy, dy, dz * dz));
                if (__builtin_expect(d2 < h[u][KNN - 1], 0)) {
                    // insert: percolate new value down the sorted list
                    float v = d2;
#pragma unroll
                    for (int i = KNN - 1; i > 0; --i) {
                        const float hp = h[u][i - 1];
                        h[u][i] = fmaxf(hp, v);
                        v       = fminf(hp, v);
                    }
                    h[u][0] = v;
                }
            }
        }
    }

    // ---- per-thread sum of the 16 exact distances ----
    float s = 0.0f;
#pragma unroll
    for (int u = 0; u < QPT; ++u)
#pragma unroll
        for (int i = 0; i < KNN; ++i) s += sqrtf(h[u][i]);

    // ---- deterministic block reduction ----
#pragma unroll
    for (int o = 16; o > 0; o >>= 1)
        s += __shfl_down_sync(0xffffffffu, s, o);

    __shared__ float ws[THREADS / 32];
    if ((tid & 31) == 0) ws[tid >> 5] = s;
    __syncthreads();
    if (tid == 0) {
        float t = 0.0f;
#pragma unroll
        for (int i = 0; i < THREADS / 32; ++i) t += ws[i];
        g_partials[bi] = t;
    }
}

__global__ __launch_bounds__(BLOCKS)
void chamfer_reduce_kernel(float* __restrict__ out)
{
    const int t = threadIdx.x;
    float v = g_partials[t];
#pragma unroll
    for (int o = 16; o > 0; o >>= 1)
        v += __shfl_down_sync(0xffffffffu, v, o);

    __shared__ float ws[BLOCKS / 32];
    if ((t & 31) == 0) ws[t >> 5] = v;
    __syncthreads();
    if (t == 0) {
        float s = 0.0f;
#pragma unroll
        for (int i = 0; i < BLOCKS / 32; ++i) s += ws[i];
        out[0] = s * (1.0f / (float)(B_ * N_ * KNN));
    }
}

extern "C" void kernel_launch(void* const* d_in, const int* in_sizes, int n_in,
                              void* d_out, int out_size)
{
    (void)in_sizes; (void)n_in; (void)out_size;
    const float* src  = (const float*)d_in[0];
    const float* tgt  = (const float*)d_in[1];
    const float* flow = (const float*)d_in[2];
    float* out = (float*)d_out;

    chamfer_knn_kernel<<<BLOCKS, THREADS>>>(src, tgt, flow);
    chamfer_reduce_kernel<<<1, BLOCKS>>>(out);
}

// round 4
// speedup vs baseline: 1.0411x; 1.0411x over previous
#include <cuda_runtime.h>
#include <math.h>

// ChamferLoss: B=4, N=8192, K=8 nearest neighbors, L2 norm.
// loss = mean over all (query, knn) exact distances, both directions.
//
// R4: packed f32x2 distance math (2 queries per instruction), candidates
// stored negated+duplicated in smem, integer (bit-pattern) threshold compares.

namespace {
constexpr int B_      = 4;
constexpr int N_      = 8192;
constexpr int KNN     = 8;
constexpr int THREADS = 128;
constexpr int QPT     = 2;                    // queries per thread (one f32x2 pair)
constexpr int QPB     = THREADS * QPT;        // 256 queries per block
constexpr int CHUNK   = 1024;                 // candidates per smem tile
constexpr int NCHUNK  = N_ / CHUNK;           // 8
constexpr int QCHUNKS = N_ / QPB;             // 32
constexpr int BLOCKS  = B_ * 2 * QCHUNKS;     // 256 (batch x dir x query-chunk)
}

typedef unsigned long long ull;

__device__ __forceinline__ ull fx2_add(ull a, ull b) {
    ull r; asm("add.rn.f32x2 %0, %1, %2;" : "=l"(r) : "l"(a), "l"(b)); return r;
}
__device__ __forceinline__ ull fx2_mul(ull a, ull b) {
    ull r; asm("mul.rn.f32x2 %0, %1, %2;" : "=l"(r) : "l"(a), "l"(b)); return r;
}
__device__ __forceinline__ ull fx2_fma(ull a, ull b, ull c) {
    ull r; asm("fma.rn.f32x2 %0, %1, %2, %3;" : "=l"(r) : "l"(a), "l"(b), "l"(c)); return r;
}
__device__ __forceinline__ ull pack2(float lo, float hi) {
    return (ull)__float_as_uint(lo) | ((ull)__float_as_uint(hi) << 32);
}
__device__ __forceinline__ ull dupf(float v) {
    unsigned u = __float_as_uint(v);
    return (ull)u | ((ull)u << 32);
}

// Deterministic reduction scratch (no atomics, no allocation).
__device__ float g_partials[BLOCKS];

__global__ __launch_bounds__(THREADS)
void chamfer_knn_kernel(const float* __restrict__ src,
                        const float* __restrict__ tgt,
                        const float* __restrict__ flow)
{
    // candidate tile: per candidate {-x,-x,-y,-y,-z,-z} = 3 x u64 (24 KB total)
    __shared__ __align__(16) ull sC[CHUNK * 3];

    const int tid    = threadIdx.x;
    const int bi     = blockIdx.x;
    const int chunkq = bi % QCHUNKS;       // which 256-query slice
    const int bd     = bi / QCHUNKS;
    const int dir    = bd & 1;             // 0: pred->tgt, 1: tgt->pred
    const int b      = bd >> 1;

    const float* __restrict__ sbase = src  + (size_t)b * N_ * 3;
    const float* __restrict__ tbase = tgt  + (size_t)b * N_ * 3;
    const float* __restrict__ fbase = flow + (size_t)b * N_ * 3;

    // ---- load this thread's two queries, packed ----
    float qx[QPT], qy[QPT], qz[QPT];
#pragma unroll
    for (int u = 0; u < QPT; ++u) {
        const int qi = chunkq * QPB + u * THREADS + tid;
        if (dir == 0) {            // query = pc_pred = src + flow
            qx[u] = sbase[3 * qi + 0] + fbase[3 * qi + 0];
            qy[u] = sbase[3 * qi + 1] + fbase[3 * qi + 1];
            qz[u] = sbase[3 * qi + 2] + fbase[3 * qi + 2];
        } else {                   // query = tgt
            qx[u] = tbase[3 * qi + 0];
            qy[u] = tbase[3 * qi + 1];
            qz[u] = tbase[3 * qi + 2];
        }
    }
    const ull qx2 = pack2(qx[0], qx[1]);
    const ull qy2 = pack2(qy[0], qy[1]);
    const ull qz2 = pack2(qz[0], qz[1]);

    // ---- per-query sorted min-8 of squared distances (ascending) ----
    float h0[KNN], h1[KNN];
#pragma unroll
    for (int i = 0; i < KNN; ++i) { h0[i] = 3.0e38f; h1[i] = 3.0e38f; }
    unsigned t0 = __float_as_uint(3.0e38f);   // bit-pattern of h0[7]
    unsigned t1 = t0;                          // bit-pattern of h1[7]

    for (int ch = 0; ch < NCHUNK; ++ch) {
        __syncthreads();   // previous tile fully consumed
        // coalesced LDG, negate, duplicate, single STS.64 per element
        const int gbase = ch * CHUNK * 3;
        for (int t = tid; t < CHUNK * 3; t += THREADS) {
            float v;
            if (dir == 0) v = -tbase[gbase + t];                       // candidates = tgt
            else          v = -(sbase[gbase + t] + fbase[gbase + t]);  // candidates = pred
            sC[t] = dupf(v);
        }
        __syncthreads();

#pragma unroll 8
        for (int j = 0; j < CHUNK; ++j) {
            const ull cx = sC[3 * j + 0];     // broadcast LDS.64 (pre-negated)
            const ull cy = sC[3 * j + 1];
            const ull cz = sC[3 * j + 2];
            const ull dx = fx2_add(qx2, cx);
            const ull dy = fx2_add(qy2, cy);
            const ull dz = fx2_add(qz2, cz);
            const ull d2 = fx2_fma(dx, dx, fx2_fma(dy, dy, fx2_mul(dz, dz)));
            const unsigned d0 = (unsigned)d2;          // low half  (query 0)
            const unsigned d1 = (unsigned)(d2 >> 32);  // high half (query 1)
            // nonnegative floats: uint compare == float compare (alu pipe)
            if (__builtin_expect(d0 < t0, 0)) {
                float v = __uint_as_float(d0);
#pragma unroll
                for (int i = KNN - 1; i > 0; --i) {
                    const float hp = h0[i - 1];
                    h0[i] = fmaxf(hp, v);
                    v     = fminf(hp, v);
                }
                h0[0] = v;
                t0 = __float_as_uint(h0[KNN - 1]);
            }
            if (__builtin_expect(d1 < t1, 0)) {
                float v = __uint_as_float(d1);
#pragma unroll
                for (int i = KNN - 1; i > 0; --i) {
                    const float hp = h1[i - 1];
                    h1[i] = fmaxf(hp, v);
                    v     = fminf(hp, v);
                }
                h1[0] = v;
                t1 = __float_as_uint(h1[KNN - 1]);
            }
        }
    }

    // ---- per-thread sum of the 16 exact distances ----
    float s = 0.0f;
#pragma unroll
    for (int i = 0; i < KNN; ++i) s += sqrtf(h0[i]) + sqrtf(h1[i]);

    // ---- deterministic block reduction ----
#pragma unroll
    for (int o = 16; o > 0; o >>= 1)
        s += __shfl_down_sync(0xffffffffu, s, o);

    __shared__ float ws[THREADS / 32];
    if ((tid & 31) == 0) ws[tid >> 5] = s;
    __syncthreads();
    if (tid == 0) {
        float t = 0.0f;
#pragma unroll
        for (int i = 0; i < THREADS / 32; ++i) t += ws[i];
        g_partials[bi] = t;
    }
}

__global__ __launch_bounds__(BLOCKS)
void chamfer_reduce_kernel(float* __restrict__ out)
{
    const int t = threadIdx.x;
    float v = g_partials[t];
#pragma unroll
    for (int o = 16; o > 0; o >>= 1)
        v += __shfl_down_sync(0xffffffffu, v, o);

    __shared__ float ws[BLOCKS / 32];
    if ((t & 31) == 0) ws[t >> 5] = v;
    __syncthreads();
    if (t == 0) {
        float s = 0.0f;
#pragma unroll
        for (int i = 0; i < BLOCKS / 32; ++i) s += ws[i];
        out[0] = s * (1.0f / (float)(B_ * N_ * KNN));
    }
}

extern "C" void kernel_launch(void* const* d_in, const int* in_sizes, int n_in,
                              void* d_out, int out_size)
{
    (void)in_sizes; (void)n_in; (void)out_size;
    const float* src  = (const float*)d_in[0];
    const float* tgt  = (const float*)d_in[1];
    const float* flow = (const float*)d_in[2];
    float* out = (float*)d_out;

    chamfer_knn_kernel<<<BLOCKS, THREADS>>>(src, tgt, flow);
    chamfer_reduce_kernel<<<1, BLOCKS>>>(out);
}

// round 5
// speedup vs baseline: 1.5115x; 1.4518x over previous
#include <cuda_runtime.h>
#include <math.h>

// ChamferLoss: B=4, N=8192, K=8 nearest neighbors, L2 norm.
// loss = mean over all (query, knn) exact distances, both directions.
//
// R5: candidate-dimension split (NSPLIT=2) to double occupancy
//     (1.7 -> 3.5 warps/SMSP), partial sorted top-8 per (query,split),
//     branchless bitonic-halver merge + sqrt + deterministic reduction.

namespace {
constexpr int B_      = 4;
constexpr int N_      = 8192;
constexpr int KNN     = 8;
constexpr int THREADS = 128;
constexpr int QPT     = 2;                     // queries per thread (one f32x2 pair)
constexpr int QPB     = THREADS * QPT;         // 256 queries per block
constexpr int NSPLIT  = 2;                     // candidate-dim split
constexpr int CANDS   = N_ / NSPLIT;           // 4096 candidates per block
constexpr int CHUNK   = 1024;                  // candidates per smem tile
constexpr int NCHUNK  = CANDS / CHUNK;         // 4
constexpr int QCHUNKS = N_ / QPB;              // 32
constexpr int BLOCKS  = B_ * 2 * QCHUNKS * NSPLIT;  // 512
constexpr int NQTOT   = B_ * 2 * N_;           // 65536 query slots (both dirs)
constexpr int MBLOCKS = NQTOT / 256;           // 256 merge blocks
}

typedef unsigned long long ull;

__device__ __forceinline__ ull fx2_add(ull a, ull b) {
    ull r; asm("add.rn.f32x2 %0, %1, %2;" : "=l"(r) : "l"(a), "l"(b)); return r;
}
__device__ __forceinline__ ull fx2_mul(ull a, ull b) {
    ull r; asm("mul.rn.f32x2 %0, %1, %2;" : "=l"(r) : "l"(a), "l"(b)); return r;
}
__device__ __forceinline__ ull fx2_fma(ull a, ull b, ull c) {
    ull r; asm("fma.rn.f32x2 %0, %1, %2, %3;" : "=l"(r) : "l"(a), "l"(b), "l"(c)); return r;
}
__device__ __forceinline__ ull pack2(float lo, float hi) {
    return (ull)__float_as_uint(lo) | ((ull)__float_as_uint(hi) << 32);
}
__device__ __forceinline__ ull dupf(float v) {
    unsigned u = __float_as_uint(v);
    return (ull)u | ((ull)u << 32);
}

// Scratch (static device globals: no allocation).
__device__ float g_knn[NSPLIT * NQTOT * KNN];   // 4 MB: sorted partial d^2 lists
__device__ float g_partials[MBLOCKS];

__global__ __launch_bounds__(THREADS)
void chamfer_knn_kernel(const float* __restrict__ src,
                        const float* __restrict__ tgt,
                        const float* __restrict__ flow)
{
    // candidate tile: per candidate {-x,-x,-y,-y,-z,-z} = 3 x u64 (24 KB)
    __shared__ __align__(16) ull sC[CHUNK * 3];

    const int tid    = threadIdx.x;
    const int bi     = blockIdx.x;
    const int split  = bi & (NSPLIT - 1);
    const int rest   = bi / NSPLIT;
    const int chunkq = rest % QCHUNKS;       // which 256-query slice
    const int bd     = rest / QCHUNKS;       // b*2 + dir
    const int dir    = bd & 1;               // 0: pred->tgt, 1: tgt->pred
    const int b      = bd >> 1;

    const float* __restrict__ sbase = src  + (size_t)b * N_ * 3;
    const float* __restrict__ tbase = tgt  + (size_t)b * N_ * 3;
    const float* __restrict__ fbase = flow + (size_t)b * N_ * 3;

    // ---- load this thread's two queries, packed ----
    float qx[QPT], qy[QPT], qz[QPT];
#pragma unroll
    for (int u = 0; u < QPT; ++u) {
        const int qi = chunkq * QPB + u * THREADS + tid;
        if (dir == 0) {            // query = pc_pred = src + flow
            qx[u] = sbase[3 * qi + 0] + fbase[3 * qi + 0];
            qy[u] = sbase[3 * qi + 1] + fbase[3 * qi + 1];
            qz[u] = sbase[3 * qi + 2] + fbase[3 * qi + 2];
        } else {                   // query = tgt
            qx[u] = tbase[3 * qi + 0];
            qy[u] = tbase[3 * qi + 1];
            qz[u] = tbase[3 * qi + 2];
        }
    }
    const ull qx2 = pack2(qx[0], qx[1]);
    const ull qy2 = pack2(qy[0], qy[1]);
    const ull qz2 = pack2(qz[0], qz[1]);

    // ---- per-query sorted min-8 of squared distances (ascending) ----
    float h0[KNN], h1[KNN];
#pragma unroll
    for (int i = 0; i < KNN; ++i) { h0[i] = 3.0e38f; h1[i] = 3.0e38f; }
    unsigned t0 = __float_as_uint(3.0e38f);   // bits of h0[7]
    unsigned t1 = t0;                          // bits of h1[7]

    for (int ch = 0; ch < NCHUNK; ++ch) {
        __syncthreads();   // previous tile fully consumed
        // coalesced LDG, negate, duplicate, one STS.64 per element
        const int gbase = (split * CANDS + ch * CHUNK) * 3;
        for (int t = tid; t < CHUNK * 3; t += THREADS) {
            float v;
            if (dir == 0) v = -tbase[gbase + t];                       // cands = tgt
            else          v = -(sbase[gbase + t] + fbase[gbase + t]);  // cands = pred
            sC[t] = dupf(v);
        }
        __syncthreads();

#pragma unroll 4
        for (int j = 0; j < CHUNK; ++j) {
            const ull cx = sC[3 * j + 0];     // broadcast LDS.64 (pre-negated)
            const ull cy = sC[3 * j + 1];
            const ull cz = sC[3 * j + 2];
            const ull dx = fx2_add(qx2, cx);
            const ull dy = fx2_add(qy2, cy);
            const ull dz = fx2_add(qz2, cz);
            const ull d2 = fx2_fma(dx, dx, fx2_fma(dy, dy, fx2_mul(dz, dz)));
            const unsigned d0 = (unsigned)d2;          // low half  (query 0)
            const unsigned d1 = (unsigned)(d2 >> 32);  // high half (query 1)
            // nonnegative floats: uint compare == float compare (alu pipe)
            if (__builtin_expect(d0 < t0, 0)) {
                float v = __uint_as_float(d0);
#pragma unroll
                for (int i = KNN - 1; i > 0; --i) {
                    const float hp = h0[i - 1];
                    h0[i] = fmaxf(hp, v);
                    v     = fminf(hp, v);
                }
                h0[0] = v;
                t0 = __float_as_uint(h0[KNN - 1]);
            }
            if (__builtin_expect(d1 < t1, 0)) {
                float v = __uint_as_float(d1);
#pragma unroll
                for (int i = KNN - 1; i > 0; --i) {
                    const float hp = h1[i - 1];
                    h1[i] = fmaxf(hp, v);
                    v     = fminf(hp, v);
                }
                h1[0] = v;
                t1 = __float_as_uint(h1[KNN - 1]);
            }
        }
    }

    // ---- write sorted partial lists (d^2) to global scratch ----
    const int qg0 = bd * N_ + chunkq * QPB + tid;            // query 0 global id
    const int qg1 = qg0 + THREADS;                           // query 1 global id
    float4* out0 = reinterpret_cast<float4*>(g_knn + ((size_t)split * NQTOT + qg0) * KNN);
    float4* out1 = reinterpret_cast<float4*>(g_knn + ((size_t)split * NQTOT + qg1) * KNN);
    out0[0] = make_float4(h0[0], h0[1], h0[2], h0[3]);
    out0[1] = make_float4(h0[4], h0[5], h0[6], h0[7]);
    out1[0] = make_float4(h1[0], h1[1], h1[2], h1[3]);
    out1[1] = make_float4(h1[4], h1[5], h1[6], h1[7]);
}

// Merge: 8 smallest of two ascending sorted 8-lists = {min(a[i], b[7-i])}
// (bitonic halver property). Sum sqrt, block-reduce deterministically.
__global__ __launch_bounds__(256)
void chamfer_merge_kernel()
{
    const int qg = blockIdx.x * 256 + threadIdx.x;
    const float4* pa = reinterpret_cast<const float4*>(g_knn + (size_t)qg * KNN);
    const float4* pb = reinterpret_cast<const float4*>(g_knn + ((size_t)NQTOT + qg) * KNN);
    const float4 a0 = pa[0], a1 = pa[1];
    const float4 b0 = pb[0], b1 = pb[1];

    float s = 0.0f;
    s += sqrtf(fminf(a0.x, b1.w));
    s += sqrtf(fminf(a0.y, b1.z));
    s += sqrtf(fminf(a0.z, b1.y));
    s += sqrtf(fminf(a0.w, b1.x));
    s += sqrtf(fminf(a1.x, b0.w));
    s += sqrtf(fminf(a1.y, b0.z));
    s += sqrtf(fminf(a1.z, b0.y));
    s += sqrtf(fminf(a1.w, b0.x));

#pragma unroll
    for (int o = 16; o > 0; o >>= 1)
        s += __shfl_down_sync(0xffffffffu, s, o);

    __shared__ float ws[8];
    if ((threadIdx.x & 31) == 0) ws[threadIdx.x >> 5] = s;
    __syncthreads();
    if (threadIdx.x == 0) {
        float t = 0.0f;
#pragma unroll
        for (int i = 0; i < 8; ++i) t += ws[i];
        g_partials[blockIdx.x] = t;
    }
}

__global__ __launch_bounds__(MBLOCKS)
void chamfer_reduce_kernel(float* __restrict__ out)
{
    const int t = threadIdx.x;
    float v = g_partials[t];
#pragma unroll
    for (int o = 16; o > 0; o >>= 1)
        v += __shfl_down_sync(0xffffffffu, v, o);

    __shared__ float ws[MBLOCKS / 32];
    if ((t & 31) == 0) ws[t >> 5] = v;
    __syncthreads();
    if (t == 0) {
        float s = 0.0f;
#pragma unroll
        for (int i = 0; i < MBLOCKS / 32; ++i) s += ws[i];
        out[0] = s * (1.0f / (float)(B_ * N_ * KNN));
    }
}

extern "C" void kernel_launch(void* const* d_in, const int* in_sizes, int n_in,
                              void* d_out, int out_size)
{
    (void)in_sizes; (void)n_in; (void)out_size;
    const float* src  = (const float*)d_in[0];
    const float* tgt  = (const float*)d_in[1];
    const float* flow = (const float*)d_in[2];
    float* out = (float*)d_out;

    chamfer_knn_kernel<<<BLOCKS, THREADS>>>(src, tgt, flow);
    chamfer_merge_kernel<<<MBLOCKS, 256>>>();
    chamfer_reduce_kernel<<<1, MBLOCKS>>>(out);
}

// round 6
// speedup vs baseline: 1.6122x; 1.0666x over previous
#include <cuda_runtime.h>
#include <math.h>

// ChamferLoss: B=4, N=8192, K=8 nearest neighbors, L2 norm.
// loss = mean over all (query, knn) exact distances, both directions.
//
// R6: NSPLIT=4 (1024 blocks -> ~27 warps/SM), smem tile as {xx,yy} LDS.128 +
//     {zz} LDS.64 (2 LDS/candidate), 4-way exact bitonic merge of partial top-8s.

namespace {
constexpr int B_      = 4;
constexpr int N_      = 8192;
constexpr int KNN     = 8;
constexpr int THREADS = 128;
constexpr int QPT     = 2;                     // queries per thread (one f32x2 pair)
constexpr int QPB     = THREADS * QPT;         // 256 queries per block
constexpr int NSPLIT  = 4;                     // candidate-dim split
constexpr int CANDS   = N_ / NSPLIT;           // 2048 candidates per block
constexpr int CHUNK   = 1024;                  // candidates per smem tile
constexpr int NCHUNK  = CANDS / CHUNK;         // 2
constexpr int QCHUNKS = N_ / QPB;              // 32
constexpr int BLOCKS  = B_ * 2 * QCHUNKS * NSPLIT;  // 1024
constexpr int NQTOT   = B_ * 2 * N_;           // 65536 query slots (both dirs)
constexpr int MBLOCKS = NQTOT / 256;           // 256 merge blocks
}

typedef unsigned long long ull;

__device__ __forceinline__ ull fx2_add(ull a, ull b) {
    ull r; asm("add.rn.f32x2 %0, %1, %2;" : "=l"(r) : "l"(a), "l"(b)); return r;
}
__device__ __forceinline__ ull fx2_mul(ull a, ull b) {
    ull r; asm("mul.rn.f32x2 %0, %1, %2;" : "=l"(r) : "l"(a), "l"(b)); return r;
}
__device__ __forceinline__ ull fx2_fma(ull a, ull b, ull c) {
    ull r; asm("fma.rn.f32x2 %0, %1, %2, %3;" : "=l"(r) : "l"(a), "l"(b), "l"(c)); return r;
}
__device__ __forceinline__ ull pack2(float lo, float hi) {
    return (ull)__float_as_uint(lo) | ((ull)__float_as_uint(hi) << 32);
}
__device__ __forceinline__ ull dupf(float v) {
    unsigned u = __float_as_uint(v);
    return (ull)u | ((ull)u << 32);
}

// Scratch (static device globals: no allocation).
__device__ float g_knn[NSPLIT * NQTOT * KNN];   // 8 MB: sorted partial d^2 lists
__device__ float g_partials[MBLOCKS];

__global__ __launch_bounds__(THREADS)
void chamfer_knn_kernel(const float* __restrict__ src,
                        const float* __restrict__ tgt,
                        const float* __restrict__ flow)
{
    // candidate tile: per candidate {-x,-x,-y,-y} (16B, LDS.128) + {-z,-z} (8B)
    __shared__ __align__(16) ulonglong2 sXY[CHUNK];   // 16 KB
    __shared__ __align__(16) ull        sZ[CHUNK];    //  8 KB

    const int tid    = threadIdx.x;
    const int bi     = blockIdx.x;
    const int split  = bi & (NSPLIT - 1);
    const int rest   = bi / NSPLIT;
    const int chunkq = rest % QCHUNKS;       // which 256-query slice
    const int bd     = rest / QCHUNKS;       // b*2 + dir
    const int dir    = bd & 1;               // 0: pred->tgt, 1: tgt->pred
    const int b      = bd >> 1;

    const float* __restrict__ sbase = src  + (size_t)b * N_ * 3;
    const float* __restrict__ tbase = tgt  + (size_t)b * N_ * 3;
    const float* __restrict__ fbase = flow + (size_t)b * N_ * 3;

    // ---- load this thread's two queries, packed ----
    float qx[QPT], qy[QPT], qz[QPT];
#pragma unroll
    for (int u = 0; u < QPT; ++u) {
        const int qi = chunkq * QPB + u * THREADS + tid;
        if (dir == 0) {            // query = pc_pred = src + flow
            qx[u] = sbase[3 * qi + 0] + fbase[3 * qi + 0];
            qy[u] = sbase[3 * qi + 1] + fbase[3 * qi + 1];
            qz[u] = sbase[3 * qi + 2] + fbase[3 * qi + 2];
        } else {                   // query = tgt
            qx[u] = tbase[3 * qi + 0];
            qy[u] = tbase[3 * qi + 1];
            qz[u] = tbase[3 * qi + 2];
        }
    }
    const ull qx2 = pack2(qx[0], qx[1]);
    const ull qy2 = pack2(qy[0], qy[1]);
    const ull qz2 = pack2(qz[0], qz[1]);

    // ---- per-query sorted min-8 of squared distances (ascending) ----
    float h0[KNN], h1[KNN];
#pragma unroll
    for (int i = 0; i < KNN; ++i) { h0[i] = 3.0e38f; h1[i] = 3.0e38f; }
    unsigned t0 = __float_as_uint(3.0e38f);   // bits of h0[7]
    unsigned t1 = t0;                          // bits of h1[7]

    for (int ch = 0; ch < NCHUNK; ++ch) {
        __syncthreads();   // previous tile fully consumed
        // coalesced LDG, negate, duplicate, one STS.64 per element
        const int gbase = (split * CANDS + ch * CHUNK) * 3;
        for (int t = tid; t < CHUNK * 3; t += THREADS) {
            float v;
            if (dir == 0) v = -tbase[gbase + t];                       // cands = tgt
            else          v = -(sbase[gbase + t] + fbase[gbase + t]);  // cands = pred
            const int p = t / 3;
            const int c = t - 3 * p;
            const ull d = dupf(v);
            if (c == 0)      sXY[p].x = d;
            else if (c == 1) sXY[p].y = d;
            else             sZ[p]    = d;
        }
        __syncthreads();

#pragma unroll 4
        for (int j = 0; j < CHUNK; ++j) {
            const ulonglong2 cxy = sXY[j];    // broadcast LDS.128 (pre-negated)
            const ull cz = sZ[j];             // broadcast LDS.64
            const ull dx = fx2_add(qx2, cxy.x);
            const ull dy = fx2_add(qy2, cxy.y);
            const ull dz = fx2_add(qz2, cz);
            const ull d2 = fx2_fma(dx, dx, fx2_fma(dy, dy, fx2_mul(dz, dz)));
            const unsigned d0 = (unsigned)d2;          // low half  (query 0)
            const unsigned d1 = (unsigned)(d2 >> 32);  // high half (query 1)
            // nonnegative floats: uint compare == float compare (alu pipe)
            if (__builtin_expect(d0 < t0, 0)) {
                float v = __uint_as_float(d0);
#pragma unroll
                for (int i = KNN - 1; i > 0; --i) {
                    const float hp = h0[i - 1];
                    h0[i] = fmaxf(hp, v);
                    v     = fminf(hp, v);
                }
                h0[0] = v;
                t0 = __float_as_uint(h0[KNN - 1]);
            }
            if (__builtin_expect(d1 < t1, 0)) {
                float v = __uint_as_float(d1);
#pragma unroll
                for (int i = KNN - 1; i > 0; --i) {
                    const float hp = h1[i - 1];
                    h1[i] = fmaxf(hp, v);
                    v     = fminf(hp, v);
                }
                h1[0] = v;
                t1 = __float_as_uint(h1[KNN - 1]);
            }
        }
    }

    // ---- write sorted partial lists (d^2) to global scratch ----
    const int qg0 = bd * N_ + chunkq * QPB + tid;            // query 0 global id
    const int qg1 = qg0 + THREADS;                           // query 1 global id
    float4* out0 = reinterpret_cast<float4*>(g_knn + ((size_t)split * NQTOT + qg0) * KNN);
    float4* out1 = reinterpret_cast<float4*>(g_knn + ((size_t)split * NQTOT + qg1) * KNN);
    out0[0] = make_float4(h0[0], h0[1], h0[2], h0[3]);
    out0[1] = make_float4(h0[4], h0[5], h0[6], h0[7]);
    out1[0] = make_float4(h1[0], h1[1], h1[2], h1[3]);
    out1[1] = make_float4(h1[4], h1[5], h1[6], h1[7]);
}

// --- exact branchless merge helpers ---
// halver: m[i] = min(a[i], b[7-i]); if a,b ascending, m = 8 smallest of a∪b (bitonic).
__device__ __forceinline__ void halver8(const float* __restrict__ a,
                                        const float* __restrict__ b,
                                        float* __restrict__ m)
{
#pragma unroll
    for (int i = 0; i < 8; ++i) m[i] = fminf(a[i], b[7 - i]);
}
// sort a bitonic 8-sequence ascending (3 compare-exchange stages).
__device__ __forceinline__ void bitonic_sort8(float* __restrict__ m)
{
#pragma unroll
    for (int st = 4; st > 0; st >>= 1)
#pragma unroll
        for (int i = 0; i < 8; ++i)
            if ((i & st) == 0) {
                const float lo = fminf(m[i], m[i + st]);
                const float hi = fmaxf(m[i], m[i + st]);
                m[i] = lo; m[i + st] = hi;
            }
}

// Merge 4 sorted partial top-8 lists per query, sum sqrt, deterministic reduce.
__global__ __launch_bounds__(256)
void chamfer_merge_kernel()
{
    const int qg = blockIdx.x * 256 + threadIdx.x;
    float L[NSPLIT][KNN];
#pragma unroll
    for (int sp = 0; sp < NSPLIT; ++sp) {
        const float4* p = reinterpret_cast<const float4*>(
            g_knn + ((size_t)sp * NQTOT + qg) * KNN);
        const float4 v0 = p[0], v1 = p[1];
        L[sp][0] = v0.x; L[sp][1] = v0.y; L[sp][2] = v0.z; L[sp][3] = v0.w;
        L[sp][4] = v1.x; L[sp][5] = v1.y; L[sp][6] = v1.z; L[sp][7] = v1.w;
    }

    float m01[8], m23[8], fin[8];
    halver8(L[0], L[1], m01); bitonic_sort8(m01);
    halver8(L[2], L[3], m23); bitonic_sort8(m23);
    halver8(m01, m23, fin);   // 8 smallest of all 32 (multiset; order irrelevant)

    float s = 0.0f;
#pragma unroll
    for (int i = 0; i < 8; ++i) s += sqrtf(fin[i]);

#pragma unroll
    for (int o = 16; o > 0; o >>= 1)
        s += __shfl_down_sync(0xffffffffu, s, o);

    __shared__ float ws[8];
    if ((threadIdx.x & 31) == 0) ws[threadIdx.x >> 5] = s;
    __syncthreads();
    if (threadIdx.x == 0) {
        float t = 0.0f;
#pragma unroll
        for (int i = 0; i < 8; ++i) t += ws[i];
        g_partials[blockIdx.x] = t;
    }
}

__global__ __launch_bounds__(MBLOCKS)
void chamfer_reduce_kernel(float* __restrict__ out)
{
    const int t = threadIdx.x;
    float v = g_partials[t];
#pragma unroll
    for (int o = 16; o > 0; o >>= 1)
        v += __shfl_down_sync(0xffffffffu, v, o);

    __shared__ float ws[MBLOCKS / 32];
    if ((t & 31) == 0) ws[t >> 5] = v;
    __syncthreads();
    if (t == 0) {
        float s = 0.0f;
#pragma unroll
        for (int i = 0; i < MBLOCKS / 32; ++i) s += ws[i];
        out[0] = s * (1.0f / (float)(B_ * N_ * KNN));
    }
}

extern "C" void kernel_launch(void* const* d_in, const int* in_sizes, int n_in,
                              void* d_out, int out_size)
{
    (void)in_sizes; (void)n_in; (void)out_size;
    const float* src  = (const float*)d_in[0];
    const float* tgt  = (const float*)d_in[1];
    const float* flow = (const float*)d_in[2];
    float* out = (float*)d_out;

    chamfer_knn_kernel<<<BLOCKS, THREADS>>>(src, tgt, flow);
    chamfer_merge_kernel<<<MBLOCKS, 256>>>();
    chamfer_reduce_kernel<<<1, MBLOCKS>>>(out);
}